// round 5
// baseline (speedup 1.0000x reference)
#include <cuda_runtime.h>

#define NN 8192
#define NE 65536

typedef unsigned long long ull;

// ---------------- zeroed scratch blob (single memset) -----------------------
#define OFF_DEG    0
#define OFF_OUTCNT 8192
#define OFF_AGG1   16384
#define OFF_AGG2   409600
#define OFF_AGGM   671744
#define OFF_AGGL   802816
#define ZFLOATS    933888
__device__ __align__(16) float g_zbuf[ZFLOATS];

// ---------------- other scratch ---------------------------------------------
__device__ __align__(16) float g_T1[NN * 48 * 8];
__device__ __align__(16) float g_Tb1[NN * 48];
__device__ __align__(16) float g_T2[NN * 32 * 8];
__device__ __align__(16) float g_Tb2[NN * 32];
__device__ __align__(16) float g_h1[NN * 48];
__device__ __align__(16) float g_hm[NN * 16];
__device__ __align__(16) float g_hl[NN * 16];
__device__ __align__(16) float g_sea[NE * 8];   // edge_attr in src-sorted order
__device__ int   g_sdst[NE];                    // dst in src-sorted order
__device__ int   g_off[NN + 1];                 // CSR offsets by src
__device__ int   g_cursor[NN];
__device__ float g_Wt1[64 * 432];
__device__ float g_Wt2[48 * 288];
__device__ float g_dinv[NN];
__device__ float g_invdeg[NN];

// ---------------- packed fp32x2 helpers (Blackwell FFMA2) -------------------
__device__ __forceinline__ void fma2(ull& d, ull a, ull b) {
    asm("fma.rn.f32x2 %0, %1, %2, %0;" : "+l"(d) : "l"(a), "l"(b));
}
__device__ __forceinline__ float2 unpack2(ull v) {
    float lo, hi;
    asm("mov.b64 {%0, %1}, %2;" : "=f"(lo), "=f"(hi) : "l"(v));
    return make_float2(lo, hi);
}

__device__ __forceinline__ void red_add_v4(float* p, float a, float b, float c, float d) {
    asm volatile("red.global.add.v4.f32 [%0], {%1,%2,%3,%4};"
                 :: "l"(p), "f"(a), "f"(b), "f"(c), "f"(d) : "memory");
}

// ---------------- prep: degree/outdeg counts + weight transposes ------------
__global__ void prep_kernel(const int* __restrict__ ei,
                            const float* __restrict__ nn1w, const float* __restrict__ nn1b,
                            const float* __restrict__ nn2w, const float* __restrict__ nn2b,
                            int* __restrict__ outcnt, int* __restrict__ deg,
                            float* __restrict__ Wt1, float* __restrict__ Wt2) {
    int bx = blockIdx.x, t = threadIdx.x;
    if (bx < 256) {
        int e = bx * 256 + t;
        atomicAdd(&outcnt[ei[e]], 1);
        atomicAdd(&deg[ei[NE + e]], 1);
    } else if (bx < 364) {               // 27648: K=64, CO=48, NC=432
        int idx = (bx - 256) * 256 + t;
        int i = idx / 432, c = idx - i * 432;
        float v;
        if (c < 384) { int o = c >> 3, s = c & 7; v = nn1w[s * 3072 + i * 48 + o]; }
        else         { int o = c - 384;           v = nn1b[i * 48 + o]; }
        Wt1[idx] = v;
    } else {                              // 13824: K=48, CO=32, NC=288
        int idx = (bx - 364) * 256 + t;
        if (idx < 13824) {
            int i = idx / 288, c = idx - i * 288;
            float v;
            if (c < 256) { int o = c >> 3, s = c & 7; v = nn2w[s * 1536 + i * 32 + o]; }
            else         { int o = c - 256;           v = nn2b[i * 32 + o]; }
            Wt2[idx] = v;
        }
    }
}

// ---------------- block 0: exclusive scan of outcnt; blocks 1..8: dinv ------
__global__ void scan_dinv_kernel(const int* __restrict__ outcnt, const int* __restrict__ deg,
                                 int* __restrict__ off, int* __restrict__ cursor,
                                 float* __restrict__ dinv, float* __restrict__ invdeg) {
    int t = threadIdx.x;
    if (blockIdx.x == 0) {
        __shared__ int wsum[32];
        int base = t * 8;
        int v[8];
        int s = 0;
#pragma unroll
        for (int j = 0; j < 8; j++) { v[j] = outcnt[base + j]; s += v[j]; }
        int lane = t & 31, wid = t >> 5;
        int inc = s;
#pragma unroll
        for (int d = 1; d < 32; d <<= 1) {
            int n = __shfl_up_sync(0xFFFFFFFFu, inc, d);
            if (lane >= d) inc += n;
        }
        int excl_warp = inc - s;
        if (lane == 31) wsum[wid] = inc;
        __syncthreads();
        if (t < 32) {
            int w = wsum[t];
            int wi = w;
#pragma unroll
            for (int d = 1; d < 32; d <<= 1) {
                int n = __shfl_up_sync(0xFFFFFFFFu, wi, d);
                if (t >= d) wi += n;
            }
            wsum[t] = wi - w;
        }
        __syncthreads();
        int run = wsum[wid] + excl_warp;
#pragma unroll
        for (int j = 0; j < 8; j++) {
            off[base + j] = run;
            cursor[base + j] = run;
            run += v[j];
        }
        if (t == 1023) off[NN] = NE;
    } else {
        int n = (blockIdx.x - 1) * 1024 + t;
        float d = (float)deg[n] + 1.0f;
        dinv[n] = rsqrtf(d);
        invdeg[n] = 1.0f / d;
    }
}

// ---------------- scatter edge payloads into src-sorted order ---------------
__global__ void perm_kernel(const int* __restrict__ ei, const float* __restrict__ ea,
                            int* __restrict__ cursor,
                            int* __restrict__ sdst, float* __restrict__ sea) {
    int e = blockIdx.x * 256 + threadIdx.x;
    int s = ei[e];
    int pos = atomicAdd(&cursor[s], 1);
    sdst[pos] = ei[NE + e];
    const float4* ev = reinterpret_cast<const float4*>(ea + e * 8);
    float4* sv = reinterpret_cast<float4*>(sea + pos * 8);
    sv[0] = ev[0];
    sv[1] = ev[1];
}

// ---------------- node GEMM via FFMA2, MOV-free operand staging -------------
// 64 nodes x 128 cols per block, 256 threads; thread = 8 nodes x 4 cols.
// smem: xsd[K][128] = x duplicated per node (float2 {v,v});
//       ws [K][128] = weight tile (natural layout; adjacent cols form f32x2).
template<int K, int CO>
__global__ void __launch_bounds__(256) node_gemm_kernel(
        const float* __restrict__ X, const float* __restrict__ Wt,
        float* __restrict__ T, float* __restrict__ Tb) {
    constexpr int NC = CO * 9;
    extern __shared__ float smem[];
    float2* xsd = reinterpret_cast<float2*>(smem);     // [K][64] float2 (dup)
    float*  ws  = smem + K * 128;                      // [K][128]
    int tid = threadIdx.x;
    int n0 = blockIdx.y * 64;
    int cbase = blockIdx.x * 128;

    // fill xsd (dup) — X tile is 64*K contiguous floats
    for (int idx = tid; idx < 64 * K; idx += 256) {
        int nl = idx / K, i = idx - nl * K;
        float v = X[(n0 + nl) * K + i];
        xsd[i * 64 + nl] = make_float2(v, v);
    }
    // fill ws
    for (int idx = tid; idx < K * 128; idx += 256) {
        int i = idx >> 7, c = idx & 127;
        int cc = cbase + c;
        ws[idx] = (cc < NC) ? Wt[i * NC + cc] : 0.f;
    }
    __syncthreads();

    int lane = tid & 31, wd = tid >> 5;
    int cl = lane * 4;
    ull acc[8][2];
#pragma unroll
    for (int j = 0; j < 8; j++) { acc[j][0] = 0ull; acc[j][1] = 0ull; }

    const ulonglong2* xrow = reinterpret_cast<const ulonglong2*>(xsd + wd * 8);
    const ulonglong2* wrow = reinterpret_cast<const ulonglong2*>(ws + cl);
#pragma unroll 8
    for (int i = 0; i < K; i++) {
        ulonglong2 wv = wrow[i * 32];          // packed (w[c],w[c+1]) , (w[c+2],w[c+3])
        ulonglong2 x0 = xrow[i * 32 + 0];      // dup pairs nodes 0,1
        ulonglong2 x1 = xrow[i * 32 + 1];      // nodes 2,3
        ulonglong2 x2 = xrow[i * 32 + 2];      // nodes 4,5
        ulonglong2 x3 = xrow[i * 32 + 3];      // nodes 6,7
        fma2(acc[0][0], x0.x, wv.x); fma2(acc[0][1], x0.x, wv.y);
        fma2(acc[1][0], x0.y, wv.x); fma2(acc[1][1], x0.y, wv.y);
        fma2(acc[2][0], x1.x, wv.x); fma2(acc[2][1], x1.x, wv.y);
        fma2(acc[3][0], x1.y, wv.x); fma2(acc[3][1], x1.y, wv.y);
        fma2(acc[4][0], x2.x, wv.x); fma2(acc[4][1], x2.x, wv.y);
        fma2(acc[5][0], x2.y, wv.x); fma2(acc[5][1], x2.y, wv.y);
        fma2(acc[6][0], x3.x, wv.x); fma2(acc[6][1], x3.x, wv.y);
        fma2(acc[7][0], x3.y, wv.x); fma2(acc[7][1], x3.y, wv.y);
    }

    int c0 = cbase + cl;
    if (c0 < NC) {
#pragma unroll
        for (int j = 0; j < 8; j++) {
            float2 v0 = unpack2(acc[j][0]);
            float2 v1 = unpack2(acc[j][1]);
            float4 r = make_float4(v0.x, v0.y, v1.x, v1.y);
            int na = n0 + wd * 8 + j;
            if (c0 < CO * 8)
                *reinterpret_cast<float4*>(T + na * (CO * 8) + c0) = r;
            else
                *reinterpret_cast<float4*>(Tb + na * CO + (c0 - CO * 8)) = r;
        }
    }
}

// ---------------- edge NNConv: node-parallel over src-CSR -------------------
template<int CO, int TPN>
__global__ void __launch_bounds__(32 * TPN) edge_nnconv_kernel(
        const int* __restrict__ off, const int* __restrict__ sdst,
        const float* __restrict__ sea,
        const float* __restrict__ T, const float* __restrict__ Tb,
        float* __restrict__ agg) {
    int t = threadIdx.x;
    int g = t / TPN;
    int o0 = (t - g * TPN) * 4;
    int n = blockIdx.x * 32 + g;

    int beg = off[n], end = off[n + 1];
    if (beg == end) return;

    const float4* tp = reinterpret_cast<const float4*>(T + (n * CO + o0) * 8);
    float4 T0 = tp[0], T1 = tp[1], T2 = tp[2], T3 = tp[3];
    float4 T4 = tp[4], T5 = tp[5], T6 = tp[6], T7 = tp[7];
    float4 bb = *reinterpret_cast<const float4*>(Tb + n * CO + o0);

    for (int e = beg; e < end; e++) {
        int dst = sdst[e];
        const float4* eap = reinterpret_cast<const float4*>(sea + e * 8);
        float4 a0 = eap[0], a1 = eap[1];
        float r0 = bb.x + a0.x * T0.x + a0.y * T0.y + a0.z * T0.z + a0.w * T0.w
                        + a1.x * T1.x + a1.y * T1.y + a1.z * T1.z + a1.w * T1.w;
        float r1 = bb.y + a0.x * T2.x + a0.y * T2.y + a0.z * T2.z + a0.w * T2.w
                        + a1.x * T3.x + a1.y * T3.y + a1.z * T3.z + a1.w * T3.w;
        float r2 = bb.z + a0.x * T4.x + a0.y * T4.y + a0.z * T4.z + a0.w * T4.w
                        + a1.x * T5.x + a1.y * T5.y + a1.z * T5.z + a1.w * T5.w;
        float r3 = bb.w + a0.x * T6.x + a0.y * T6.y + a0.z * T6.z + a0.w * T6.w
                        + a1.x * T7.x + a1.y * T7.y + a1.z * T7.z + a1.w * T7.w;
        red_add_v4(agg + dst * CO + o0, r0, r1, r2, r3);
    }
}

// ---------------- H = relu(agg + X @ root + bias) ---------------------------
template<int K, int CO>
__global__ void root_relu_kernel(const float* __restrict__ agg, const float* __restrict__ X,
                                 const float* __restrict__ root, const float* __restrict__ bias,
                                 float* __restrict__ H) {
    constexpr int NB = 16;
    constexpr int ITEMS = NB * CO / 256;
    __shared__ float xs[NB][K];
    int n0 = blockIdx.x * NB;
    for (int idx = threadIdx.x; idx < NB * K; idx += 256)
        xs[idx / K][idx % K] = X[n0 * K + idx];
    __syncthreads();
#pragma unroll
    for (int j = 0; j < ITEMS; j++) {
        int item = threadIdx.x + j * 256;
        int nl = item / CO, o = item - nl * CO;
        float acc = agg[(n0 + nl) * CO + o] + bias[o];
#pragma unroll 4
        for (int i = 0; i < K; i++) acc += xs[nl][i] * root[i * CO + o];
        H[(n0 + nl) * CO + o] = fmaxf(acc, 0.f);
    }
}

// ---------------- fused: h2 = relu(...); hm = h2@muw; hl = h2@lsw -----------
__global__ void root2_heads_kernel(const float* __restrict__ agg, const float* __restrict__ H1,
                                   const float* __restrict__ root, const float* __restrict__ bias,
                                   const float* __restrict__ muw, const float* __restrict__ lsw,
                                   float* __restrict__ hm, float* __restrict__ hl) {
    __shared__ float xs[16][48];
    __shared__ float hs[16][32];
    int n0 = blockIdx.x * 16;
    for (int idx = threadIdx.x; idx < 16 * 48; idx += 256)
        xs[idx / 48][idx % 48] = H1[n0 * 48 + idx];
    __syncthreads();
#pragma unroll
    for (int j = 0; j < 2; j++) {
        int item = threadIdx.x + j * 256;
        int nl = item >> 5, o = item & 31;
        float acc = agg[(n0 + nl) * 32 + o] + bias[o];
#pragma unroll 4
        for (int i = 0; i < 48; i++) acc += xs[nl][i] * root[i * 32 + o];
        hs[nl][o] = fmaxf(acc, 0.f);
    }
    __syncthreads();
#pragma unroll
    for (int j = 0; j < 2; j++) {
        int item = threadIdx.x + j * 256;
        int nl = item >> 5;
        int r = item & 31;
        int head = r >> 4, o = r & 15;
        const float* W = head ? lsw : muw;
        float acc = 0.f;
#pragma unroll
        for (int i = 0; i < 32; i++) acc += hs[nl][i] * W[i * 16 + o];
        (head ? hl : hm)[(n0 + nl) * 16 + o] = acc;
    }
}

// ---------------- GCN scatter: node-parallel over src-CSR -------------------
__global__ void __launch_bounds__(256) gcn_edge_kernel(
        const int* __restrict__ off, const int* __restrict__ sdst,
        const float* __restrict__ hm, const float* __restrict__ hl,
        const float* __restrict__ dinv,
        float* __restrict__ aggm, float* __restrict__ aggl) {
    int t = threadIdx.x;
    int g = t >> 3;
    int r = t & 7;
    int head = r >> 2, q = r & 3;
    int n = blockIdx.x * 32 + g;
    int beg = off[n], end = off[n + 1];
    if (beg == end) return;

    const float* h = head ? hl : hm;
    float* a = head ? aggl : aggm;
    float4 v = *reinterpret_cast<const float4*>(h + n * 16 + q * 4);
    float ds = dinv[n];
    for (int e = beg; e < end; e++) {
        int dst = sdst[e];
        float w = ds * dinv[dst];
        red_add_v4(a + dst * 16 + q * 4, v.x * w, v.y * w, v.z * w, v.w * w);
    }
}

// ---------------- final: out = agg + h*invdeg + bias (mu then ls) -----------
__global__ void out_kernel(const float* __restrict__ aggm, const float* __restrict__ aggl,
                           const float* __restrict__ hm, const float* __restrict__ hl,
                           const float* __restrict__ invdeg, const float* __restrict__ mub,
                           const float* __restrict__ lsb, float* __restrict__ out) {
    int i4 = blockIdx.x * 256 + threadIdx.x;
    int n = i4 >> 2, q = i4 & 3;
    float iv = invdeg[n];
    float4* out4 = reinterpret_cast<float4*>(out);
    float4 am = reinterpret_cast<const float4*>(aggm)[i4];
    float4 vm = reinterpret_cast<const float4*>(hm)[i4];
    float4 bm = reinterpret_cast<const float4*>(mub)[q];
    out4[i4] = make_float4(am.x + vm.x * iv + bm.x, am.y + vm.y * iv + bm.y,
                           am.z + vm.z * iv + bm.z, am.w + vm.w * iv + bm.w);
    float4 al = reinterpret_cast<const float4*>(aggl)[i4];
    float4 vl = reinterpret_cast<const float4*>(hl)[i4];
    float4 bl = reinterpret_cast<const float4*>(lsb)[q];
    out4[32768 + i4] = make_float4(al.x + vl.x * iv + bl.x, al.y + vl.y * iv + bl.y,
                                   al.z + vl.z * iv + bl.z, al.w + vl.w * iv + bl.w);
}

// ---------------- launcher --------------------------------------------------
extern "C" void kernel_launch(void* const* d_in, const int* in_sizes, int n_in,
                              void* d_out, int out_size) {
    const float* x      = (const float*)d_in[0];
    const int*   ei     = (const int*)  d_in[1];
    const float* ea     = (const float*)d_in[2];
    const float* nn1_w  = (const float*)d_in[3];
    const float* nn1_b  = (const float*)d_in[4];
    const float* root1  = (const float*)d_in[5];
    const float* bias1  = (const float*)d_in[6];
    const float* nn2_w  = (const float*)d_in[7];
    const float* nn2_b  = (const float*)d_in[8];
    const float* root2  = (const float*)d_in[9];
    const float* bias2  = (const float*)d_in[10];
    const float* mu_w   = (const float*)d_in[11];
    const float* mu_b   = (const float*)d_in[12];
    const float* ls_w   = (const float*)d_in[13];
    const float* ls_b   = (const float*)d_in[14];
    float* out = (float*)d_out;

    void *pz, *pT1, *pTb1, *pT2, *pTb2, *ph1, *phm, *phl;
    void *pWt1, *pWt2, *pdinv, *pinvdeg, *poff, *pcur, *psdst, *psea;
    cudaGetSymbolAddress(&pz, g_zbuf);
    cudaGetSymbolAddress(&pT1, g_T1);
    cudaGetSymbolAddress(&pTb1, g_Tb1);
    cudaGetSymbolAddress(&pT2, g_T2);
    cudaGetSymbolAddress(&pTb2, g_Tb2);
    cudaGetSymbolAddress(&ph1, g_h1);
    cudaGetSymbolAddress(&phm, g_hm);
    cudaGetSymbolAddress(&phl, g_hl);
    cudaGetSymbolAddress(&pWt1, g_Wt1);
    cudaGetSymbolAddress(&pWt2, g_Wt2);
    cudaGetSymbolAddress(&pdinv, g_dinv);
    cudaGetSymbolAddress(&pinvdeg, g_invdeg);
    cudaGetSymbolAddress(&poff, g_off);
    cudaGetSymbolAddress(&pcur, g_cursor);
    cudaGetSymbolAddress(&psdst, g_sdst);
    cudaGetSymbolAddress(&psea, g_sea);

    float* zb = (float*)pz;
    int*   deg    = (int*)(zb + OFF_DEG);
    int*   outcnt = (int*)(zb + OFF_OUTCNT);
    float* agg1   = zb + OFF_AGG1;
    float* agg2   = zb + OFF_AGG2;
    float* aggm   = zb + OFF_AGGM;
    float* aggl   = zb + OFF_AGGL;

    cudaFuncSetAttribute(node_gemm_kernel<64, 48>,
                         cudaFuncAttributeMaxDynamicSharedMemorySize, 64 * 1024);
    cudaFuncSetAttribute(node_gemm_kernel<48, 32>,
                         cudaFuncAttributeMaxDynamicSharedMemorySize, 48 * 1024);

    cudaMemsetAsync(pz, 0, ZFLOATS * sizeof(float), 0);

    prep_kernel<<<418, 256>>>(ei, nn1_w, nn1_b, nn2_w, nn2_b,
                              outcnt, deg, (float*)pWt1, (float*)pWt2);
    scan_dinv_kernel<<<9, 1024>>>(outcnt, deg, (int*)poff, (int*)pcur,
                                  (float*)pdinv, (float*)pinvdeg);
    perm_kernel<<<256, 256>>>(ei, ea, (int*)pcur, (int*)psdst, (float*)psea);

    // layer 1
    node_gemm_kernel<64, 48><<<dim3(4, 128), 256, 64 * 1024>>>(
        x, (float*)pWt1, (float*)pT1, (float*)pTb1);
    edge_nnconv_kernel<48, 12><<<NN / 32, 384>>>((int*)poff, (int*)psdst, (float*)psea,
                                                 (float*)pT1, (float*)pTb1, agg1);
    root_relu_kernel<64, 48><<<NN / 16, 256>>>(agg1, x, root1, bias1, (float*)ph1);

    // layer 2
    node_gemm_kernel<48, 32><<<dim3(3, 128), 256, 48 * 1024>>>(
        (float*)ph1, (float*)pWt2, (float*)pT2, (float*)pTb2);
    edge_nnconv_kernel<32, 8><<<NN / 32, 256>>>((int*)poff, (int*)psdst, (float*)psea,
                                                (float*)pT2, (float*)pTb2, agg2);
    root2_heads_kernel<<<NN / 16, 256>>>(agg2, (float*)ph1, root2, bias2,
                                         mu_w, ls_w, (float*)phm, (float*)phl);

    // GCN scatter + output
    gcn_edge_kernel<<<NN / 32, 256>>>((int*)poff, (int*)psdst, (float*)phm, (float*)phl,
                                      (float*)pdinv, aggm, aggl);
    out_kernel<<<128, 256>>>(aggm, aggl, (float*)phm, (float*)phl,
                             (float*)pinvdeg, mu_b, ls_b, out);
}

// round 6
// speedup vs baseline: 1.0192x; 1.0192x over previous
#include <cuda_runtime.h>

#define NN 8192
#define NE 65536

typedef unsigned long long ull;

// ---------------- zeroed scratch blob (single memset) -----------------------
#define OFF_DEG    0
#define OFF_OUTCNT 8192
#define OFF_AGG1   16384
#define OFF_AGG2   409600
#define OFF_AGGM   671744
#define OFF_AGGL   802816
#define ZFLOATS    933888
__device__ __align__(16) float g_zbuf[ZFLOATS];

// ---------------- other scratch ---------------------------------------------
__device__ __align__(16) float g_T1[NN * 48 * 8];
__device__ __align__(16) float g_Tb1[NN * 48];
__device__ __align__(16) float g_T2[NN * 32 * 8];
__device__ __align__(16) float g_Tb2[NN * 32];
__device__ __align__(16) float g_h1[NN * 48];
__device__ __align__(16) float g_hm[NN * 16];
__device__ __align__(16) float g_hl[NN * 16];
__device__ __align__(16) float g_sea[NE * 8];   // edge_attr in src-sorted order
__device__ int   g_sdst[NE];                    // dst in src-sorted order
__device__ int   g_off[NN + 1];                 // CSR offsets by src
__device__ int   g_cursor[NN];
__device__ __align__(16) float g_Wt1[64 * 432];
__device__ __align__(16) float g_Wt2[48 * 288];
__device__ float g_dinv[NN];
__device__ float g_invdeg[NN];

// ---------------- packed fp32x2 helpers (Blackwell FFMA2) -------------------
__device__ __forceinline__ void fma2(ull& d, ull a, ull b) {
    asm("fma.rn.f32x2 %0, %1, %2, %0;" : "+l"(d) : "l"(a), "l"(b));
}
__device__ __forceinline__ float2 unpack2(ull v) {
    float lo, hi;
    asm("mov.b64 {%0, %1}, %2;" : "=f"(lo), "=f"(hi) : "l"(v));
    return make_float2(lo, hi);
}

__device__ __forceinline__ void red_add_v4(float* p, float a, float b, float c, float d) {
    asm volatile("red.global.add.v4.f32 [%0], {%1,%2,%3,%4};"
                 :: "l"(p), "f"(a), "f"(b), "f"(c), "f"(d) : "memory");
}

// ---------------- prep: degree/outdeg counts + weight transposes ------------
__global__ void prep_kernel(const int* __restrict__ ei,
                            const float* __restrict__ nn1w, const float* __restrict__ nn1b,
                            const float* __restrict__ nn2w, const float* __restrict__ nn2b,
                            int* __restrict__ outcnt, int* __restrict__ deg,
                            float* __restrict__ Wt1, float* __restrict__ Wt2) {
    int bx = blockIdx.x, t = threadIdx.x;
    if (bx < 256) {
        int e = bx * 256 + t;
        atomicAdd(&outcnt[ei[e]], 1);
        atomicAdd(&deg[ei[NE + e]], 1);
    } else if (bx < 364) {               // 27648: K=64, CO=48, NC=432
        int idx = (bx - 256) * 256 + t;
        int i = idx / 432, c = idx - i * 432;
        float v;
        if (c < 384) { int o = c >> 3, s = c & 7; v = nn1w[s * 3072 + i * 48 + o]; }
        else         { int o = c - 384;           v = nn1b[i * 48 + o]; }
        Wt1[idx] = v;
    } else {                              // 13824: K=48, CO=32, NC=288
        int idx = (bx - 364) * 256 + t;
        if (idx < 13824) {
            int i = idx / 288, c = idx - i * 288;
            float v;
            if (c < 256) { int o = c >> 3, s = c & 7; v = nn2w[s * 1536 + i * 32 + o]; }
            else         { int o = c - 256;           v = nn2b[i * 32 + o]; }
            Wt2[idx] = v;
        }
    }
}

// ---------------- block 0: exclusive scan of outcnt; blocks 1..8: dinv ------
__global__ void scan_dinv_kernel(const int* __restrict__ outcnt, const int* __restrict__ deg,
                                 int* __restrict__ off, int* __restrict__ cursor,
                                 float* __restrict__ dinv, float* __restrict__ invdeg) {
    int t = threadIdx.x;
    if (blockIdx.x == 0) {
        __shared__ int wsum[32];
        int base = t * 8;
        int v[8];
        int s = 0;
#pragma unroll
        for (int j = 0; j < 8; j++) { v[j] = outcnt[base + j]; s += v[j]; }
        int lane = t & 31, wid = t >> 5;
        int inc = s;
#pragma unroll
        for (int d = 1; d < 32; d <<= 1) {
            int n = __shfl_up_sync(0xFFFFFFFFu, inc, d);
            if (lane >= d) inc += n;
        }
        int excl_warp = inc - s;
        if (lane == 31) wsum[wid] = inc;
        __syncthreads();
        if (t < 32) {
            int w = wsum[t];
            int wi = w;
#pragma unroll
            for (int d = 1; d < 32; d <<= 1) {
                int n = __shfl_up_sync(0xFFFFFFFFu, wi, d);
                if (t >= d) wi += n;
            }
            wsum[t] = wi - w;
        }
        __syncthreads();
        int run = wsum[wid] + excl_warp;
#pragma unroll
        for (int j = 0; j < 8; j++) {
            off[base + j] = run;
            cursor[base + j] = run;
            run += v[j];
        }
        if (t == 1023) off[NN] = NE;
    } else {
        int n = (blockIdx.x - 1) * 1024 + t;
        float d = (float)deg[n] + 1.0f;
        dinv[n] = rsqrtf(d);
        invdeg[n] = 1.0f / d;
    }
}

// ---------------- scatter edge payloads into src-sorted order ---------------
__global__ void perm_kernel(const int* __restrict__ ei, const float* __restrict__ ea,
                            int* __restrict__ cursor,
                            int* __restrict__ sdst, float* __restrict__ sea) {
    int e = blockIdx.x * 256 + threadIdx.x;
    int s = ei[e];
    int pos = atomicAdd(&cursor[s], 1);
    sdst[pos] = ei[NE + e];
    const float4* ev = reinterpret_cast<const float4*>(ea + e * 8);
    float4* sv = reinterpret_cast<float4*>(sea + pos * 8);
    sv[0] = ev[0];
    sv[1] = ev[1];
}

// ---------------- node GEMM via FFMA2: x dup'd in smem, w via LDG.128 -------
// 64 nodes x 128 cols per block, 256 threads; thread = 8 nodes x 4 cols.
// smem = xsd[K][64] float2 only (32KB @ K=64) -> single-wave occupancy.
template<int K, int CO>
__global__ void __launch_bounds__(256) node_gemm_kernel(
        const float* __restrict__ X, const float* __restrict__ Wt,
        float* __restrict__ T, float* __restrict__ Tb) {
    constexpr int NC = CO * 9;
    extern __shared__ float2 xsd[];                    // [K][64] duplicated pairs
    int tid = threadIdx.x;
    int n0 = blockIdx.y * 64;
    int cbase = blockIdx.x * 128;

    // conflict-free fill: consecutive threads -> consecutive nl (adjacent float2)
    for (int idx = tid; idx < 64 * K; idx += 256) {
        int i = idx >> 6, nl = idx & 63;
        float v = X[(n0 + nl) * K + i];
        xsd[i * 64 + nl] = make_float2(v, v);
    }
    __syncthreads();

    int lane = tid & 31, wd = tid >> 5;
    int cl = lane * 4;
    int c0 = cbase + cl;
    bool act = c0 < NC;

    ull acc[8][2];
#pragma unroll
    for (int j = 0; j < 8; j++) { acc[j][0] = 0ull; acc[j][1] = 0ull; }

    const ulonglong2* xrow = reinterpret_cast<const ulonglong2*>(xsd + wd * 8);
    const float* wbase = Wt + c0;
#pragma unroll 4
    for (int i = 0; i < K; i++) {
        ulonglong2 wv = act
            ? __ldg(reinterpret_cast<const ulonglong2*>(wbase + i * NC))
            : make_ulonglong2(0ull, 0ull);
        ulonglong2 x0 = xrow[i * 32 + 0];      // dup pairs: nodes 0,1
        ulonglong2 x1 = xrow[i * 32 + 1];      // nodes 2,3
        ulonglong2 x2 = xrow[i * 32 + 2];      // nodes 4,5
        ulonglong2 x3 = xrow[i * 32 + 3];      // nodes 6,7
        fma2(acc[0][0], x0.x, wv.x); fma2(acc[0][1], x0.x, wv.y);
        fma2(acc[1][0], x0.y, wv.x); fma2(acc[1][1], x0.y, wv.y);
        fma2(acc[2][0], x1.x, wv.x); fma2(acc[2][1], x1.x, wv.y);
        fma2(acc[3][0], x1.y, wv.x); fma2(acc[3][1], x1.y, wv.y);
        fma2(acc[4][0], x2.x, wv.x); fma2(acc[4][1], x2.x, wv.y);
        fma2(acc[5][0], x2.y, wv.x); fma2(acc[5][1], x2.y, wv.y);
        fma2(acc[6][0], x3.x, wv.x); fma2(acc[6][1], x3.x, wv.y);
        fma2(acc[7][0], x3.y, wv.x); fma2(acc[7][1], x3.y, wv.y);
    }

    if (act) {
#pragma unroll
        for (int j = 0; j < 8; j++) {
            float2 v0 = unpack2(acc[j][0]);
            float2 v1 = unpack2(acc[j][1]);
            float4 r = make_float4(v0.x, v0.y, v1.x, v1.y);
            int na = n0 + wd * 8 + j;
            if (c0 < CO * 8)
                *reinterpret_cast<float4*>(T + na * (CO * 8) + c0) = r;
            else
                *reinterpret_cast<float4*>(Tb + na * CO + (c0 - CO * 8)) = r;
        }
    }
}

// ---------------- edge NNConv: node-parallel over src-CSR -------------------
template<int CO, int TPN>
__global__ void __launch_bounds__(32 * TPN) edge_nnconv_kernel(
        const int* __restrict__ off, const int* __restrict__ sdst,
        const float* __restrict__ sea,
        const float* __restrict__ T, const float* __restrict__ Tb,
        float* __restrict__ agg) {
    int t = threadIdx.x;
    int g = t / TPN;
    int o0 = (t - g * TPN) * 4;
    int n = blockIdx.x * 32 + g;

    int beg = off[n], end = off[n + 1];
    if (beg == end) return;

    const float4* tp = reinterpret_cast<const float4*>(T + (n * CO + o0) * 8);
    float4 T0 = tp[0], T1 = tp[1], T2 = tp[2], T3 = tp[3];
    float4 T4 = tp[4], T5 = tp[5], T6 = tp[6], T7 = tp[7];
    float4 bb = *reinterpret_cast<const float4*>(Tb + n * CO + o0);

    for (int e = beg; e < end; e++) {
        int dst = sdst[e];
        const float4* eap = reinterpret_cast<const float4*>(sea + e * 8);
        float4 a0 = eap[0], a1 = eap[1];
        float r0 = bb.x + a0.x * T0.x + a0.y * T0.y + a0.z * T0.z + a0.w * T0.w
                        + a1.x * T1.x + a1.y * T1.y + a1.z * T1.z + a1.w * T1.w;
        float r1 = bb.y + a0.x * T2.x + a0.y * T2.y + a0.z * T2.z + a0.w * T2.w
                        + a1.x * T3.x + a1.y * T3.y + a1.z * T3.z + a1.w * T3.w;
        float r2 = bb.z + a0.x * T4.x + a0.y * T4.y + a0.z * T4.z + a0.w * T4.w
                        + a1.x * T5.x + a1.y * T5.y + a1.z * T5.z + a1.w * T5.w;
        float r3 = bb.w + a0.x * T6.x + a0.y * T6.y + a0.z * T6.z + a0.w * T6.w
                        + a1.x * T7.x + a1.y * T7.y + a1.z * T7.z + a1.w * T7.w;
        red_add_v4(agg + dst * CO + o0, r0, r1, r2, r3);
    }
}

// ---------------- H = relu(agg + X @ root + bias) ---------------------------
template<int K, int CO>
__global__ void root_relu_kernel(const float* __restrict__ agg, const float* __restrict__ X,
                                 const float* __restrict__ root, const float* __restrict__ bias,
                                 float* __restrict__ H) {
    constexpr int NB = 16;
    constexpr int ITEMS = NB * CO / 256;
    __shared__ float xs[NB][K];
    int n0 = blockIdx.x * NB;
    for (int idx = threadIdx.x; idx < NB * K; idx += 256)
        xs[idx / K][idx % K] = X[n0 * K + idx];
    __syncthreads();
#pragma unroll
    for (int j = 0; j < ITEMS; j++) {
        int item = threadIdx.x + j * 256;
        int nl = item / CO, o = item - nl * CO;
        float acc = agg[(n0 + nl) * CO + o] + bias[o];
#pragma unroll 4
        for (int i = 0; i < K; i++) acc += xs[nl][i] * root[i * CO + o];
        H[(n0 + nl) * CO + o] = fmaxf(acc, 0.f);
    }
}

// ---------------- fused: h2 = relu(...); hm = h2@muw; hl = h2@lsw -----------
__global__ void root2_heads_kernel(const float* __restrict__ agg, const float* __restrict__ H1,
                                   const float* __restrict__ root, const float* __restrict__ bias,
                                   const float* __restrict__ muw, const float* __restrict__ lsw,
                                   float* __restrict__ hm, float* __restrict__ hl) {
    __shared__ float xs[16][48];
    __shared__ float hs[16][32];
    int n0 = blockIdx.x * 16;
    for (int idx = threadIdx.x; idx < 16 * 48; idx += 256)
        xs[idx / 48][idx % 48] = H1[n0 * 48 + idx];
    __syncthreads();
#pragma unroll
    for (int j = 0; j < 2; j++) {
        int item = threadIdx.x + j * 256;
        int nl = item >> 5, o = item & 31;
        float acc = agg[(n0 + nl) * 32 + o] + bias[o];
#pragma unroll 4
        for (int i = 0; i < 48; i++) acc += xs[nl][i] * root[i * 32 + o];
        hs[nl][o] = fmaxf(acc, 0.f);
    }
    __syncthreads();
#pragma unroll
    for (int j = 0; j < 2; j++) {
        int item = threadIdx.x + j * 256;
        int nl = item >> 5;
        int r = item & 31;
        int head = r >> 4, o = r & 15;
        const float* W = head ? lsw : muw;
        float acc = 0.f;
#pragma unroll
        for (int i = 0; i < 32; i++) acc += hs[nl][i] * W[i * 16 + o];
        (head ? hl : hm)[(n0 + nl) * 16 + o] = acc;
    }
}

// ---------------- GCN scatter: node-parallel over src-CSR -------------------
__global__ void __launch_bounds__(256) gcn_edge_kernel(
        const int* __restrict__ off, const int* __restrict__ sdst,
        const float* __restrict__ hm, const float* __restrict__ hl,
        const float* __restrict__ dinv,
        float* __restrict__ aggm, float* __restrict__ aggl) {
    int t = threadIdx.x;
    int g = t >> 3;
    int r = t & 7;
    int head = r >> 2, q = r & 3;
    int n = blockIdx.x * 32 + g;
    int beg = off[n], end = off[n + 1];
    if (beg == end) return;

    const float* h = head ? hl : hm;
    float* a = head ? aggl : aggm;
    float4 v = *reinterpret_cast<const float4*>(h + n * 16 + q * 4);
    float ds = dinv[n];
    for (int e = beg; e < end; e++) {
        int dst = sdst[e];
        float w = ds * dinv[dst];
        red_add_v4(a + dst * 16 + q * 4, v.x * w, v.y * w, v.z * w, v.w * w);
    }
}

// ---------------- final: out = agg + h*invdeg + bias (mu then ls) -----------
__global__ void out_kernel(const float* __restrict__ aggm, const float* __restrict__ aggl,
                           const float* __restrict__ hm, const float* __restrict__ hl,
                           const float* __restrict__ invdeg, const float* __restrict__ mub,
                           const float* __restrict__ lsb, float* __restrict__ out) {
    int i4 = blockIdx.x * 256 + threadIdx.x;
    int n = i4 >> 2, q = i4 & 3;
    float iv = invdeg[n];
    float4* out4 = reinterpret_cast<float4*>(out);
    float4 am = reinterpret_cast<const float4*>(aggm)[i4];
    float4 vm = reinterpret_cast<const float4*>(hm)[i4];
    float4 bm = reinterpret_cast<const float4*>(mub)[q];
    out4[i4] = make_float4(am.x + vm.x * iv + bm.x, am.y + vm.y * iv + bm.y,
                           am.z + vm.z * iv + bm.z, am.w + vm.w * iv + bm.w);
    float4 al = reinterpret_cast<const float4*>(aggl)[i4];
    float4 vl = reinterpret_cast<const float4*>(hl)[i4];
    float4 bl = reinterpret_cast<const float4*>(lsb)[q];
    out4[32768 + i4] = make_float4(al.x + vl.x * iv + bl.x, al.y + vl.y * iv + bl.y,
                                   al.z + vl.z * iv + bl.z, al.w + vl.w * iv + bl.w);
}

// ---------------- launcher --------------------------------------------------
extern "C" void kernel_launch(void* const* d_in, const int* in_sizes, int n_in,
                              void* d_out, int out_size) {
    const float* x      = (const float*)d_in[0];
    const int*   ei     = (const int*)  d_in[1];
    const float* ea     = (const float*)d_in[2];
    const float* nn1_w  = (const float*)d_in[3];
    const float* nn1_b  = (const float*)d_in[4];
    const float* root1  = (const float*)d_in[5];
    const float* bias1  = (const float*)d_in[6];
    const float* nn2_w  = (const float*)d_in[7];
    const float* nn2_b  = (const float*)d_in[8];
    const float* root2  = (const float*)d_in[9];
    const float* bias2  = (const float*)d_in[10];
    const float* mu_w   = (const float*)d_in[11];
    const float* mu_b   = (const float*)d_in[12];
    const float* ls_w   = (const float*)d_in[13];
    const float* ls_b   = (const float*)d_in[14];
    float* out = (float*)d_out;

    void *pz, *pT1, *pTb1, *pT2, *pTb2, *ph1, *phm, *phl;
    void *pWt1, *pWt2, *pdinv, *pinvdeg, *poff, *pcur, *psdst, *psea;
    cudaGetSymbolAddress(&pz, g_zbuf);
    cudaGetSymbolAddress(&pT1, g_T1);
    cudaGetSymbolAddress(&pTb1, g_Tb1);
    cudaGetSymbolAddress(&pT2, g_T2);
    cudaGetSymbolAddress(&pTb2, g_Tb2);
    cudaGetSymbolAddress(&ph1, g_h1);
    cudaGetSymbolAddress(&phm, g_hm);
    cudaGetSymbolAddress(&phl, g_hl);
    cudaGetSymbolAddress(&pWt1, g_Wt1);
    cudaGetSymbolAddress(&pWt2, g_Wt2);
    cudaGetSymbolAddress(&pdinv, g_dinv);
    cudaGetSymbolAddress(&pinvdeg, g_invdeg);
    cudaGetSymbolAddress(&poff, g_off);
    cudaGetSymbolAddress(&pcur, g_cursor);
    cudaGetSymbolAddress(&psdst, g_sdst);
    cudaGetSymbolAddress(&psea, g_sea);

    float* zb = (float*)pz;
    int*   deg    = (int*)(zb + OFF_DEG);
    int*   outcnt = (int*)(zb + OFF_OUTCNT);
    float* agg1   = zb + OFF_AGG1;
    float* agg2   = zb + OFF_AGG2;
    float* aggm   = zb + OFF_AGGM;
    float* aggl   = zb + OFF_AGGL;

    cudaMemsetAsync(pz, 0, ZFLOATS * sizeof(float), 0);

    prep_kernel<<<418, 256>>>(ei, nn1_w, nn1_b, nn2_w, nn2_b,
                              outcnt, deg, (float*)pWt1, (float*)pWt2);
    scan_dinv_kernel<<<9, 1024>>>(outcnt, deg, (int*)poff, (int*)pcur,
                                  (float*)pdinv, (float*)pinvdeg);
    perm_kernel<<<256, 256>>>(ei, ea, (int*)pcur, (int*)psdst, (float*)psea);

    // layer 1  (dyn smem: 64 nodes * K floats duplicated = K*512 bytes)
    node_gemm_kernel<64, 48><<<dim3(4, 128), 256, 64 * 512>>>(
        x, (float*)pWt1, (float*)pT1, (float*)pTb1);
    edge_nnconv_kernel<48, 12><<<NN / 32, 384>>>((int*)poff, (int*)psdst, (float*)psea,
                                                 (float*)pT1, (float*)pTb1, agg1);
    root_relu_kernel<64, 48><<<NN / 16, 256>>>(agg1, x, root1, bias1, (float*)ph1);

    // layer 2
    node_gemm_kernel<48, 32><<<dim3(3, 128), 256, 48 * 512>>>(
        (float*)ph1, (float*)pWt2, (float*)pT2, (float*)pTb2);
    edge_nnconv_kernel<32, 8><<<NN / 32, 256>>>((int*)poff, (int*)psdst, (float*)psea,
                                                (float*)pT2, (float*)pTb2, agg2);
    root2_heads_kernel<<<NN / 16, 256>>>(agg2, (float*)ph1, root2, bias2,
                                         mu_w, ls_w, (float*)phm, (float*)phl);

    // GCN scatter + output
    gcn_edge_kernel<<<NN / 32, 256>>>((int*)poff, (int*)psdst, (float*)phm, (float*)phl,
                                      (float*)pdinv, aggm, aggl);
    out_kernel<<<128, 256>>>(aggm, aggl, (float*)phm, (float*)phl,
                             (float*)pinvdeg, mu_b, ls_b, out);
}

// round 7
// speedup vs baseline: 1.0827x; 1.0624x over previous
#include <cuda_runtime.h>

#define NN 8192
#define NE 65536

typedef unsigned long long ull;

// ---------------- zeroed scratch blob (single memset) -----------------------
#define OFF_DEG    0
#define OFF_OUTCNT 8192
#define OFF_AGG1   16384
#define OFF_AGG2   409600
#define OFF_AGGM   671744
#define OFF_AGGL   802816
#define ZFLOATS    933888
__device__ __align__(16) float g_zbuf[ZFLOATS];

// ---------------- other scratch ---------------------------------------------
__device__ __align__(16) float g_T1[NN * 48 * 8];
__device__ __align__(16) float g_Tb1[NN * 48];
__device__ __align__(16) float g_T2[NN * 32 * 8];
__device__ __align__(16) float g_Tb2[NN * 32];
__device__ __align__(16) float g_h1[NN * 48];
__device__ __align__(16) float g_hm[NN * 16];
__device__ __align__(16) float g_hl[NN * 16];
__device__ __align__(16) float g_sea[NE * 8];   // edge_attr in src-sorted order
__device__ int   g_sdst[NE];                    // dst in src-sorted order
__device__ int   g_off[NN + 1];                 // CSR offsets by src
__device__ int   g_cursor[NN];
// pair-interleaved weights: Wtp[(k/2)*(2*NC) + c*2 + (k&1)] = W[k][c]
__device__ __align__(16) float g_Wtp1[64 * 432];
__device__ __align__(16) float g_Wtp2[48 * 288];
__device__ float g_dinv[NN];
__device__ float g_invdeg[NN];

// ---------------- packed fp32x2 helpers (Blackwell FFMA2) -------------------
__device__ __forceinline__ void fma2(ull& d, ull a, ull b) {
    asm("fma.rn.f32x2 %0, %1, %2, %0;" : "+l"(d) : "l"(a), "l"(b));
}
__device__ __forceinline__ float2 unpack2(ull v) {
    float lo, hi;
    asm("mov.b64 {%0, %1}, %2;" : "=f"(lo), "=f"(hi) : "l"(v));
    return make_float2(lo, hi);
}

__device__ __forceinline__ void red_add_v4(float* p, float a, float b, float c, float d) {
    asm volatile("red.global.add.v4.f32 [%0], {%1,%2,%3,%4};"
                 :: "l"(p), "f"(a), "f"(b), "f"(c), "f"(d) : "memory");
}

// ---------------- prep: degree/outdeg counts + pair-interleaved weights -----
__global__ void prep_kernel(const int* __restrict__ ei,
                            const float* __restrict__ nn1w, const float* __restrict__ nn1b,
                            const float* __restrict__ nn2w, const float* __restrict__ nn2b,
                            int* __restrict__ outcnt, int* __restrict__ deg,
                            float* __restrict__ Wtp1, float* __restrict__ Wtp2) {
    int bx = blockIdx.x, t = threadIdx.x;
    if (bx < 256) {
        int e = bx * 256 + t;
        atomicAdd(&outcnt[ei[e]], 1);
        atomicAdd(&deg[ei[NE + e]], 1);
    } else if (bx < 364) {               // 27648 elems: K=64, CO=48, NC=432
        int idx = (bx - 256) * 256 + t;
        int i2 = idx / 864, rem = idx - i2 * 864;
        int c = rem >> 1, i = i2 * 2 + (rem & 1);
        float v;
        if (c < 384) { int o = c >> 3, s = c & 7; v = nn1w[s * 3072 + i * 48 + o]; }
        else         { int o = c - 384;           v = nn1b[i * 48 + o]; }
        Wtp1[idx] = v;
    } else {                              // 13824 elems: K=48, CO=32, NC=288
        int idx = (bx - 364) * 256 + t;
        if (idx < 13824) {
            int i2 = idx / 576, rem = idx - i2 * 576;
            int c = rem >> 1, i = i2 * 2 + (rem & 1);
            float v;
            if (c < 256) { int o = c >> 3, s = c & 7; v = nn2w[s * 1536 + i * 32 + o]; }
            else         { int o = c - 256;           v = nn2b[i * 32 + o]; }
            Wtp2[idx] = v;
        }
    }
}

// ---------------- block 0: exclusive scan of outcnt; blocks 1..8: dinv ------
__global__ void scan_dinv_kernel(const int* __restrict__ outcnt, const int* __restrict__ deg,
                                 int* __restrict__ off, int* __restrict__ cursor,
                                 float* __restrict__ dinv, float* __restrict__ invdeg) {
    int t = threadIdx.x;
    if (blockIdx.x == 0) {
        __shared__ int wsum[32];
        int base = t * 8;
        int v[8];
        int s = 0;
#pragma unroll
        for (int j = 0; j < 8; j++) { v[j] = outcnt[base + j]; s += v[j]; }
        int lane = t & 31, wid = t >> 5;
        int inc = s;
#pragma unroll
        for (int d = 1; d < 32; d <<= 1) {
            int n = __shfl_up_sync(0xFFFFFFFFu, inc, d);
            if (lane >= d) inc += n;
        }
        int excl_warp = inc - s;
        if (lane == 31) wsum[wid] = inc;
        __syncthreads();
        if (t < 32) {
            int w = wsum[t];
            int wi = w;
#pragma unroll
            for (int d = 1; d < 32; d <<= 1) {
                int n = __shfl_up_sync(0xFFFFFFFFu, wi, d);
                if (t >= d) wi += n;
            }
            wsum[t] = wi - w;
        }
        __syncthreads();
        int run = wsum[wid] + excl_warp;
#pragma unroll
        for (int j = 0; j < 8; j++) {
            off[base + j] = run;
            cursor[base + j] = run;
            run += v[j];
        }
        if (t == 1023) off[NN] = NE;
    } else {
        int n = (blockIdx.x - 1) * 1024 + t;
        float d = (float)deg[n] + 1.0f;
        dinv[n] = rsqrtf(d);
        invdeg[n] = 1.0f / d;
    }
}

// ---------------- scatter edge payloads into src-sorted order ---------------
__global__ void perm_kernel(const int* __restrict__ ei, const float* __restrict__ ea,
                            int* __restrict__ cursor,
                            int* __restrict__ sdst, float* __restrict__ sea) {
    int e = blockIdx.x * 256 + threadIdx.x;
    int s = ei[e];
    int pos = atomicAdd(&cursor[s], 1);
    sdst[pos] = ei[NE + e];
    const float4* ev = reinterpret_cast<const float4*>(ea + e * 8);
    float4* sv = reinterpret_cast<float4*>(sea + pos * 8);
    sv[0] = ev[0];
    sv[1] = ev[1];
}

// ---------------- node GEMM: k-paired FFMA2, conflict-free operands ---------
// Block: 256 thr, 32 nodes x 128 cols per tile, 2 tiles. Thread: 4 nodes x
// 4 cols (c = cbase + lane + 32j). acc pairs over k-parity; result = lo+hi.
template<int K, int CO>
__global__ void __launch_bounds__(256, 4) node_gemm_kernel(
        const float* __restrict__ X, const float* __restrict__ Wtp,
        float* __restrict__ T, float* __restrict__ Tb) {
    constexpr int NC = CO * 9;
    constexpr int KH = K / 2;
    __shared__ __align__(16) float ws[KH * 256];   // [kpair][colpair*2]
    __shared__ __align__(16) float xs[32 * K];     // node-major
    int tid = threadIdx.x;
    int cbase = blockIdx.x * 128;

    // fill ws as ull pairs: wsu[r*128 + j] = (W[2r][cbase+j], W[2r+1][cbase+j])
    {
        ull* wsu = reinterpret_cast<ull*>(ws);
        const ull* Wu = reinterpret_cast<const ull*>(Wtp);
        for (int idx = tid; idx < KH * 128; idx += 256) {
            int r = idx >> 7, j = idx & 127;
            int c = cbase + j;
            wsu[idx] = (c < NC) ? Wu[r * NC + c] : 0ull;
        }
    }

    int lane = tid & 31, wd = tid >> 5;
    const ull* wsu = reinterpret_cast<const ull*>(ws);
    const float4* X4 = reinterpret_cast<const float4*>(X);
    float4* xs4 = reinterpret_cast<float4*>(xs);

    for (int tile = 0; tile < 2; tile++) {
        int n0 = (blockIdx.y * 2 + tile) * 32;
        __syncthreads();
        for (int idx = tid; idx < 32 * K / 4; idx += 256)
            xs4[idx] = X4[n0 * (K / 4) + idx];
        __syncthreads();

        ull acc[4][4];
#pragma unroll
        for (int n = 0; n < 4; n++)
#pragma unroll
            for (int j = 0; j < 4; j++) acc[n][j] = 0ull;

        const ulonglong2* xrow =
            reinterpret_cast<const ulonglong2*>(xs + (wd * 4) * K);
#pragma unroll 4
        for (int kk = 0; kk < K / 4; kk++) {
            ulonglong2 xv0 = xrow[0 * (K / 4) + kk];
            ulonglong2 xv1 = xrow[1 * (K / 4) + kk];
            ulonglong2 xv2 = xrow[2 * (K / 4) + kk];
            ulonglong2 xv3 = xrow[3 * (K / 4) + kk];
            // k-pair row r0 = 2kk (k = 4kk, 4kk+1)
            {
                const ull* wr = wsu + (2 * kk) * 128 + lane;
                ull w0 = wr[0], w1 = wr[32], w2 = wr[64], w3 = wr[96];
                fma2(acc[0][0], xv0.x, w0); fma2(acc[0][1], xv0.x, w1);
                fma2(acc[0][2], xv0.x, w2); fma2(acc[0][3], xv0.x, w3);
                fma2(acc[1][0], xv1.x, w0); fma2(acc[1][1], xv1.x, w1);
                fma2(acc[1][2], xv1.x, w2); fma2(acc[1][3], xv1.x, w3);
                fma2(acc[2][0], xv2.x, w0); fma2(acc[2][1], xv2.x, w1);
                fma2(acc[2][2], xv2.x, w2); fma2(acc[2][3], xv2.x, w3);
                fma2(acc[3][0], xv3.x, w0); fma2(acc[3][1], xv3.x, w1);
                fma2(acc[3][2], xv3.x, w2); fma2(acc[3][3], xv3.x, w3);
            }
            // k-pair row r1 = 2kk+1 (k = 4kk+2, 4kk+3)
            {
                const ull* wr = wsu + (2 * kk + 1) * 128 + lane;
                ull w0 = wr[0], w1 = wr[32], w2 = wr[64], w3 = wr[96];
                fma2(acc[0][0], xv0.y, w0); fma2(acc[0][1], xv0.y, w1);
                fma2(acc[0][2], xv0.y, w2); fma2(acc[0][3], xv0.y, w3);
                fma2(acc[1][0], xv1.y, w0); fma2(acc[1][1], xv1.y, w1);
                fma2(acc[1][2], xv1.y, w2); fma2(acc[1][3], xv1.y, w3);
                fma2(acc[2][0], xv2.y, w0); fma2(acc[2][1], xv2.y, w1);
                fma2(acc[2][2], xv2.y, w2); fma2(acc[2][3], xv2.y, w3);
                fma2(acc[3][0], xv3.y, w0); fma2(acc[3][1], xv3.y, w1);
                fma2(acc[3][2], xv3.y, w2); fma2(acc[3][3], xv3.y, w3);
            }
        }

#pragma unroll
        for (int n = 0; n < 4; n++) {
            int na = n0 + wd * 4 + n;
#pragma unroll
            for (int j = 0; j < 4; j++) {
                int c = cbase + lane + 32 * j;
                if (c < NC) {
                    float2 p = unpack2(acc[n][j]);
                    float v = p.x + p.y;
                    if (c < CO * 8) T[na * (CO * 8) + c] = v;
                    else            Tb[na * CO + (c - CO * 8)] = v;
                }
            }
        }
    }
}

// ---------------- edge NNConv: node-parallel over src-CSR -------------------
template<int CO, int TPN>
__global__ void __launch_bounds__(32 * TPN) edge_nnconv_kernel(
        const int* __restrict__ off, const int* __restrict__ sdst,
        const float* __restrict__ sea,
        const float* __restrict__ T, const float* __restrict__ Tb,
        float* __restrict__ agg) {
    int t = threadIdx.x;
    int g = t / TPN;
    int o0 = (t - g * TPN) * 4;
    int n = blockIdx.x * 32 + g;

    int beg = off[n], end = off[n + 1];
    if (beg == end) return;

    const float4* tp = reinterpret_cast<const float4*>(T + (n * CO + o0) * 8);
    float4 T0 = tp[0], T1 = tp[1], T2 = tp[2], T3 = tp[3];
    float4 T4 = tp[4], T5 = tp[5], T6 = tp[6], T7 = tp[7];
    float4 bb = *reinterpret_cast<const float4*>(Tb + n * CO + o0);

    for (int e = beg; e < end; e++) {
        int dst = sdst[e];
        const float4* eap = reinterpret_cast<const float4*>(sea + e * 8);
        float4 a0 = eap[0], a1 = eap[1];
        float r0 = bb.x + a0.x * T0.x + a0.y * T0.y + a0.z * T0.z + a0.w * T0.w
                        + a1.x * T1.x + a1.y * T1.y + a1.z * T1.z + a1.w * T1.w;
        float r1 = bb.y + a0.x * T2.x + a0.y * T2.y + a0.z * T2.z + a0.w * T2.w
                        + a1.x * T3.x + a1.y * T3.y + a1.z * T3.z + a1.w * T3.w;
        float r2 = bb.z + a0.x * T4.x + a0.y * T4.y + a0.z * T4.z + a0.w * T4.w
                        + a1.x * T5.x + a1.y * T5.y + a1.z * T5.z + a1.w * T5.w;
        float r3 = bb.w + a0.x * T6.x + a0.y * T6.y + a0.z * T6.z + a0.w * T6.w
                        + a1.x * T7.x + a1.y * T7.y + a1.z * T7.z + a1.w * T7.w;
        red_add_v4(agg + dst * CO + o0, r0, r1, r2, r3);
    }
}

// ---------------- H = relu(agg + X @ root + bias) ---------------------------
template<int K, int CO>
__global__ void root_relu_kernel(const float* __restrict__ agg, const float* __restrict__ X,
                                 const float* __restrict__ root, const float* __restrict__ bias,
                                 float* __restrict__ H) {
    constexpr int NB = 16;
    constexpr int ITEMS = NB * CO / 256;
    __shared__ float xs[NB][K];
    int n0 = blockIdx.x * NB;
    for (int idx = threadIdx.x; idx < NB * K; idx += 256)
        xs[idx / K][idx % K] = X[n0 * K + idx];
    __syncthreads();
#pragma unroll
    for (int j = 0; j < ITEMS; j++) {
        int item = threadIdx.x + j * 256;
        int nl = item / CO, o = item - nl * CO;
        float acc = agg[(n0 + nl) * CO + o] + bias[o];
#pragma unroll 4
        for (int i = 0; i < K; i++) acc += xs[nl][i] * root[i * CO + o];
        H[(n0 + nl) * CO + o] = fmaxf(acc, 0.f);
    }
}

// ---------------- fused: h2 = relu(...); hm = h2@muw; hl = h2@lsw -----------
__global__ void root2_heads_kernel(const float* __restrict__ agg, const float* __restrict__ H1,
                                   const float* __restrict__ root, const float* __restrict__ bias,
                                   const float* __restrict__ muw, const float* __restrict__ lsw,
                                   float* __restrict__ hm, float* __restrict__ hl) {
    __shared__ float xs[16][48];
    __shared__ float hs[16][32];
    int n0 = blockIdx.x * 16;
    for (int idx = threadIdx.x; idx < 16 * 48; idx += 256)
        xs[idx / 48][idx % 48] = H1[n0 * 48 + idx];
    __syncthreads();
#pragma unroll
    for (int j = 0; j < 2; j++) {
        int item = threadIdx.x + j * 256;
        int nl = item >> 5, o = item & 31;
        float acc = agg[(n0 + nl) * 32 + o] + bias[o];
#pragma unroll 4
        for (int i = 0; i < 48; i++) acc += xs[nl][i] * root[i * 32 + o];
        hs[nl][o] = fmaxf(acc, 0.f);
    }
    __syncthreads();
#pragma unroll
    for (int j = 0; j < 2; j++) {
        int item = threadIdx.x + j * 256;
        int nl = item >> 5;
        int r = item & 31;
        int head = r >> 4, o = r & 15;
        const float* W = head ? lsw : muw;
        float acc = 0.f;
#pragma unroll
        for (int i = 0; i < 32; i++) acc += hs[nl][i] * W[i * 16 + o];
        (head ? hl : hm)[(n0 + nl) * 16 + o] = acc;
    }
}

// ---------------- GCN scatter: node-parallel over src-CSR -------------------
__global__ void __launch_bounds__(256) gcn_edge_kernel(
        const int* __restrict__ off, const int* __restrict__ sdst,
        const float* __restrict__ hm, const float* __restrict__ hl,
        const float* __restrict__ dinv,
        float* __restrict__ aggm, float* __restrict__ aggl) {
    int t = threadIdx.x;
    int g = t >> 3;
    int r = t & 7;
    int head = r >> 2, q = r & 3;
    int n = blockIdx.x * 32 + g;
    int beg = off[n], end = off[n + 1];
    if (beg == end) return;

    const float* h = head ? hl : hm;
    float* a = head ? aggl : aggm;
    float4 v = *reinterpret_cast<const float4*>(h + n * 16 + q * 4);
    float ds = dinv[n];
    for (int e = beg; e < end; e++) {
        int dst = sdst[e];
        float w = ds * dinv[dst];
        red_add_v4(a + dst * 16 + q * 4, v.x * w, v.y * w, v.z * w, v.w * w);
    }
}

// ---------------- final: out = agg + h*invdeg + bias (mu then ls) -----------
__global__ void out_kernel(const float* __restrict__ aggm, const float* __restrict__ aggl,
                           const float* __restrict__ hm, const float* __restrict__ hl,
                           const float* __restrict__ invdeg, const float* __restrict__ mub,
                           const float* __restrict__ lsb, float* __restrict__ out) {
    int i4 = blockIdx.x * 256 + threadIdx.x;
    int n = i4 >> 2, q = i4 & 3;
    float iv = invdeg[n];
    float4* out4 = reinterpret_cast<float4*>(out);
    float4 am = reinterpret_cast<const float4*>(aggm)[i4];
    float4 vm = reinterpret_cast<const float4*>(hm)[i4];
    float4 bm = reinterpret_cast<const float4*>(mub)[q];
    out4[i4] = make_float4(am.x + vm.x * iv + bm.x, am.y + vm.y * iv + bm.y,
                           am.z + vm.z * iv + bm.z, am.w + vm.w * iv + bm.w);
    float4 al = reinterpret_cast<const float4*>(aggl)[i4];
    float4 vl = reinterpret_cast<const float4*>(hl)[i4];
    float4 bl = reinterpret_cast<const float4*>(lsb)[q];
    out4[32768 + i4] = make_float4(al.x + vl.x * iv + bl.x, al.y + vl.y * iv + bl.y,
                                   al.z + vl.z * iv + bl.z, al.w + vl.w * iv + bl.w);
}

// ---------------- launcher --------------------------------------------------
extern "C" void kernel_launch(void* const* d_in, const int* in_sizes, int n_in,
                              void* d_out, int out_size) {
    const float* x      = (const float*)d_in[0];
    const int*   ei     = (const int*)  d_in[1];
    const float* ea     = (const float*)d_in[2];
    const float* nn1_w  = (const float*)d_in[3];
    const float* nn1_b  = (const float*)d_in[4];
    const float* root1  = (const float*)d_in[5];
    const float* bias1  = (const float*)d_in[6];
    const float* nn2_w  = (const float*)d_in[7];
    const float* nn2_b  = (const float*)d_in[8];
    const float* root2  = (const float*)d_in[9];
    const float* bias2  = (const float*)d_in[10];
    const float* mu_w   = (const float*)d_in[11];
    const float* mu_b   = (const float*)d_in[12];
    const float* ls_w   = (const float*)d_in[13];
    const float* ls_b   = (const float*)d_in[14];
    float* out = (float*)d_out;

    void *pz, *pT1, *pTb1, *pT2, *pTb2, *ph1, *phm, *phl;
    void *pWtp1, *pWtp2, *pdinv, *pinvdeg, *poff, *pcur, *psdst, *psea;
    cudaGetSymbolAddress(&pz, g_zbuf);
    cudaGetSymbolAddress(&pT1, g_T1);
    cudaGetSymbolAddress(&pTb1, g_Tb1);
    cudaGetSymbolAddress(&pT2, g_T2);
    cudaGetSymbolAddress(&pTb2, g_Tb2);
    cudaGetSymbolAddress(&ph1, g_h1);
    cudaGetSymbolAddress(&phm, g_hm);
    cudaGetSymbolAddress(&phl, g_hl);
    cudaGetSymbolAddress(&pWtp1, g_Wtp1);
    cudaGetSymbolAddress(&pWtp2, g_Wtp2);
    cudaGetSymbolAddress(&pdinv, g_dinv);
    cudaGetSymbolAddress(&pinvdeg, g_invdeg);
    cudaGetSymbolAddress(&poff, g_off);
    cudaGetSymbolAddress(&pcur, g_cursor);
    cudaGetSymbolAddress(&psdst, g_sdst);
    cudaGetSymbolAddress(&psea, g_sea);

    float* zb = (float*)pz;
    int*   deg    = (int*)(zb + OFF_DEG);
    int*   outcnt = (int*)(zb + OFF_OUTCNT);
    float* agg1   = zb + OFF_AGG1;
    float* agg2   = zb + OFF_AGG2;
    float* aggm   = zb + OFF_AGGM;
    float* aggl   = zb + OFF_AGGL;

    cudaMemsetAsync(pz, 0, ZFLOATS * sizeof(float), 0);

    prep_kernel<<<418, 256>>>(ei, nn1_w, nn1_b, nn2_w, nn2_b,
                              outcnt, deg, (float*)pWtp1, (float*)pWtp2);
    scan_dinv_kernel<<<9, 1024>>>(outcnt, deg, (int*)poff, (int*)pcur,
                                  (float*)pdinv, (float*)pinvdeg);
    perm_kernel<<<256, 256>>>(ei, ea, (int*)pcur, (int*)psdst, (float*)psea);

    // layer 1
    node_gemm_kernel<64, 48><<<dim3(4, 128), 256>>>(
        x, (float*)pWtp1, (float*)pT1, (float*)pTb1);
    edge_nnconv_kernel<48, 12><<<NN / 32, 384>>>((int*)poff, (int*)psdst, (float*)psea,
                                                 (float*)pT1, (float*)pTb1, agg1);
    root_relu_kernel<64, 48><<<NN / 16, 256>>>(agg1, x, root1, bias1, (float*)ph1);

    // layer 2
    node_gemm_kernel<48, 32><<<dim3(3, 128), 256>>>(
        (float*)ph1, (float*)pWtp2, (float*)pT2, (float*)pTb2);
    edge_nnconv_kernel<32, 8><<<NN / 32, 256>>>((int*)poff, (int*)psdst, (float*)psea,
                                                (float*)pT2, (float*)pTb2, agg2);
    root2_heads_kernel<<<NN / 16, 256>>>(agg2, (float*)ph1, root2, bias2,
                                         mu_w, ls_w, (float*)phm, (float*)phl);

    // GCN scatter + output
    gcn_edge_kernel<<<NN / 32, 256>>>((int*)poff, (int*)psdst, (float*)phm, (float*)phl,
                                      (float*)pdinv, aggm, aggl);
    out_kernel<<<128, 256>>>(aggm, aggl, (float*)phm, (float*)phl,
                             (float*)pinvdeg, mu_b, ls_b, out);
}